// round 13
// baseline (speedup 1.0000x reference)
#include <cuda_runtime.h>
#include <math.h>

// Fixed shapes: xs/hat_xs are (16, 65536, 3) float32 -> 1,048,576 vectors, 65,536 groups of 16.
#define NGROUPS      65536
#define TPG          2                      // threads per group (8 exps each)
#define THREADS      256
#define GPB          (THREADS / TPG)        // 128 groups per block
#define NBLOCKS      (NGROUPS / GPB)        // 512
#define PAIRS_MASK   2047
#define N0_DROP      5
#define DT           0.01f
#define INV_HUBER    200.0f
#define AOE_COEF     (0.2f / 65536.0f)
#define HUB_COEF     (1.25f / 98064.0f)     // 0.1*W*HUBER^2/2 / (16*2043*3)
#define PI_F         3.14159265358979f

// q = (x,y,z,w), w scalar. Hamilton product (R(a)R(b)).
__device__ __forceinline__ float4 qmul(float4 a, float4 b) {
    float4 r;
    r.w = a.w * b.w - a.x * b.x - a.y * b.y - a.z * b.z;
    r.x = a.w * b.x + a.x * b.w + a.y * b.z - a.z * b.y;
    r.y = a.w * b.y - a.x * b.z + a.y * b.w + a.z * b.x;
    r.z = a.w * b.z + a.x * b.y - a.y * b.x + a.z * b.w;
    return r;
}

// conj(a) * b
__device__ __forceinline__ float4 qcmul(float4 a, float4 b) {
    float4 r;
    r.w = a.w * b.w + a.x * b.x + a.y * b.y + a.z * b.z;
    r.x = a.w * b.x - a.x * b.w - a.y * b.z + a.z * b.y;
    r.y = a.w * b.y + a.x * b.z - a.y * b.w - a.z * b.x;
    r.z = a.w * b.z - a.x * b.y + a.y * b.x - a.z * b.w;
    return r;
}

// exp of small rotation vector (|v| <= ~0.1), Taylor in (a/2)^2, err ~1e-12
__device__ __forceinline__ float4 qexp_small(float x, float y, float z) {
    float a2 = fmaf(x, x, fmaf(y, y, z * z));
    float t2 = 0.25f * a2;
    float w  = fmaf(t2, fmaf(t2, (1.0f / 24.0f), -0.5f), 1.0f);           // cos(a/2)
    float k  = fmaf(t2, fmaf(t2, (0.5f / 120.0f), -(0.5f / 6.0f)), 0.5f); // sin(a/2)/a
    return make_float4(k * x, k * y, k * z, w);
}

// full-range exp via MUFU (X = exp(xs))
__device__ __forceinline__ float4 qexp_full(float x, float y, float z) {
    float a2 = fmaf(x, x, fmaf(y, y, z * z));
    float a  = sqrtf(fmaxf(a2, 1e-16f));
    float h  = 0.5f * a;
    float s  = __sinf(h);
    float c  = __cosf(h);
    float k  = __fdividef(s, a);
    if (a2 < 1e-8f) k = 0.5f;
    return make_float4(k * x, k * y, k * z, c);
}

// acos for x in [0,1]: A&S 4.4.45, abs err <= 6.7e-5 rad, ~6 instr
__device__ __forceinline__ float acos01(float x) {
    float p = fmaf(x, -0.0187293f, 0.0742610f);
    p = fmaf(p, x, -0.2121144f);
    p = fmaf(p, x, 1.5707288f);
    return sqrtf(1.0f - x) * p;
}

// acos for x in [-1,1] (branch-free select)
__device__ __forceinline__ float acos_full(float x) {
    float r = acos01(fabsf(x));
    return (x < 0.0f) ? (PI_F - r) : r;
}

__device__ __forceinline__ float huber_elem(float r) {
    float ar = fabsf(r);
    return (ar < 1.0f) ? 0.5f * r * r : ar - 0.5f;
}

__device__ __forceinline__ float4 shfl_down4(float4 v, int d) {
    float4 r;
    r.x = __shfl_down_sync(0xffffffffu, v.x, d);
    r.y = __shfl_down_sync(0xffffffffu, v.y, d);
    r.z = __shfl_down_sync(0xffffffffu, v.z, d);
    r.w = __shfl_down_sync(0xffffffffu, v.w, d);
    return r;
}

__global__ __launch_bounds__(THREADS)
void loss_kernel(const float* __restrict__ xs, const float* __restrict__ hat,
                 float* __restrict__ out) {
    const int tid = threadIdx.x;
    const int t   = tid & 1;                       // sub-thread within group
    const int n   = blockIdx.x * GPB + (tid >> 1); // group index 0..65535

    // ---- early xs load (even lanes) so DRAM latency hides under the chain
    float4 xv = make_float4(0.f, 0.f, 0.f, 0.f);
    if (t == 0) xv = reinterpret_cast<const float4*>(xs)[(size_t)n * 12];

    // ---- this thread's 8 vectors = 6 float4 (96B contiguous, MLP=6)
    const float4* hp = reinterpret_cast<const float4*>(hat) + (size_t)n * 12 + t * 6;
    float4 v0 = hp[0], v1 = hp[1], v2 = hp[2], v3 = hp[3], v4 = hp[4], v5 = hp[5];

    // ---- 8 small exps, binary-tree combined (7 qmuls, depth 3)
    float4 q0 = qexp_small(DT * v0.x, DT * v0.y, DT * v0.z);
    float4 q1 = qexp_small(DT * v0.w, DT * v1.x, DT * v1.y);
    float4 q2 = qexp_small(DT * v1.z, DT * v1.w, DT * v2.x);
    float4 q3 = qexp_small(DT * v2.y, DT * v2.z, DT * v2.w);
    float4 q4 = qexp_small(DT * v3.x, DT * v3.y, DT * v3.z);
    float4 q5 = qexp_small(DT * v3.w, DT * v4.x, DT * v4.y);
    float4 q6 = qexp_small(DT * v4.z, DT * v4.w, DT * v5.x);
    float4 q7 = qexp_small(DT * v5.y, DT * v5.z, DT * v5.w);
    float4 H  = qmul(qmul(qmul(q0, q1), qmul(q2, q3)),
                     qmul(qmul(q4, q5), qmul(q6, q7)));

    // ---- partner merge: Omega for group n lives on even lanes (t==0)
    float4 Ho = shfl_down4(H, 1);
    float4 Om = qmul(H, Ho);

    // ---- X_n = exp(xs_flat[16n])
    float4 X = qexp_full(xv.x, xv.y, xv.z);

    // ---- AOE: angle = 2*acos(|<qOm,qX>|), masked to even lanes
    float d   = fmaf(Om.w, X.w, fmaf(Om.x, X.x, fmaf(Om.y, X.y, Om.z * X.z)));
    float ch  = fminf(fabsf(d), 1.0f);
    float ang = 2.0f * acos01(ch);
    float aoe = (t == 0) ? ang * ang : 0.0f;
    float hub = 0.0f;

    // ---- pyramid level: pair group 2m (lane 4m%32) with 2m+1 (lane +2)
    float4 Omo = shfl_down4(Om, 2);
    float4 Xo  = shfl_down4(X, 2);

    if (t == 0 && (n & 1) == 0) {
        int m = n >> 1;
        if ((m & PAIRS_MASK) >= N0_DROP) {
            float4 Op  = qmul(Om, Omo);
            float4 Xp  = qmul(X, Xo);
            float4 rel = qcmul(Op, Xp);              // Op^T * Xp
            float w  = rel.w;
            float ct = fminf(fmaxf(fmaf(2.0f * w, w, -1.0f), -1.0f), 1.0f);
            float an = acos_full(ct);
            float sv = sqrtf(fmaxf(1.0f - w * w, 0.0f));
            float st = 2.0f * fabsf(w) * sv;         // sin(theta)
            float factor = (st < 1e-6f) ? 0.5f : __fdividef(an, 2.0f * st);
            float fh = factor * 4.0f * w * INV_HUBER;
            hub = huber_elem(fh * rel.x) + huber_elem(fh * rel.y) + huber_elem(fh * rel.z);
        }
    }

    // ---- warp reduction
#pragma unroll
    for (int o = 16; o > 0; o >>= 1) {
        aoe += __shfl_xor_sync(0xffffffffu, aoe, o);
        hub += __shfl_xor_sync(0xffffffffu, hub, o);
    }

    // ---- block combine (8 warps) + one scaled RED per block
    __shared__ float s_aoe[THREADS / 32], s_hub[THREADS / 32];
    const int wid = tid >> 5, lid = tid & 31;
    if (lid == 0) { s_aoe[wid] = aoe; s_hub[wid] = hub; }
    __syncthreads();
    if (tid == 0) {
        float ba = 0.0f, bh = 0.0f;
#pragma unroll
        for (int i = 0; i < THREADS / 32; i++) { ba += s_aoe[i]; bh += s_hub[i]; }
        atomicAdd(out, fmaf(AOE_COEF, ba, HUB_COEF * bh));   // RED.ADD.F32
    }
}

extern "C" void kernel_launch(void* const* d_in, const int* in_sizes, int n_in,
                              void* d_out, int out_size) {
    const float* xs  = (const float*)d_in[0];
    const float* hat = (const float*)d_in[1];
    (void)in_sizes; (void)n_in; (void)out_size;
    cudaMemsetAsync(d_out, 0, sizeof(float), (cudaStream_t)0);  // graph-capturable memset node
    loss_kernel<<<NBLOCKS, THREADS, 0, (cudaStream_t)0>>>(xs, hat, (float*)d_out);
}